// round 9
// baseline (speedup 1.0000x reference)
#include <cuda_runtime.h>
#include <cuda_bf16.h>
#include <cstdint>
#include <math.h>

// ============================================================================
// QAConv: s[g,p,i,j] = <ker[p,i,:], gal[g,:,j]> (channel-L2-normalized),
// score[g,p] = sigmoid( lbn( fc( bn( [colmax_i | rowmax_j] ) ) ) / 10 )
//
// sm_103 (no 'a' features available in this build): warp-level mma.sync bf16
// + ldmatrix + cp.async double-buffered pipeline. One CTA per (g,p) pair,
// register-resident 192x192 accumulator, fused dual-max epilogue.
// ============================================================================

#define G_ 64
#define P_ 64
#define D_ 512
#define HW_ 192

__device__ __nv_bfloat16 g_kerA[(size_t)P_ * HW_ * D_];   // [p][i][k]  K-major
__device__ __nv_bfloat16 g_galB[(size_t)G_ * HW_ * D_];   // [g][j][k]  K-major
__device__ float g_scale[128 * HW_];                      // [z][j]

// ------------------------------ Kernel 1: norms ------------------------------
__global__ void norm_kernel(const float* __restrict__ gal,
                            const float* __restrict__ prob) {
    int b = blockIdx.x;            // 0..127
    int j = threadIdx.x;           // 0..191
    const float* src = (b < 64) ? (gal + (size_t)b * D_ * HW_)
                                : (prob + (size_t)(b - 64) * D_ * HW_);
    float ss = 0.f;
#pragma unroll 8
    for (int d = 0; d < D_; d++) {
        float v = src[(size_t)d * HW_ + j];
        ss += v * v;
    }
    float n = sqrtf(ss);
    g_scale[b * HW_ + j] = 1.f / fmaxf(n, 1e-12f);
}

// --------------------- Kernel 2: transpose + scale + bf16 --------------------
__global__ void prep_kernel(const float* __restrict__ gal,
                            const float* __restrict__ prob) {
    __shared__ float tile[32][33];
    int z = blockIdx.z;                 // 0..127
    int d0 = blockIdx.x * 32;           // 16 tiles
    int j0 = blockIdx.y * 32;           // 6 tiles
    int tx = threadIdx.x, ty = threadIdx.y;  // 32 x 8
    const float* src;
    __nv_bfloat16* dst;
    if (z < 64) {
        src = gal + (size_t)z * D_ * HW_;
        dst = g_galB + (size_t)z * HW_ * D_;
    } else {
        src = prob + (size_t)(z - 64) * D_ * HW_;
        dst = g_kerA + (size_t)(z - 64) * HW_ * D_;
    }
#pragma unroll
    for (int r = 0; r < 32; r += 8)
        tile[ty + r][tx] = src[(size_t)(d0 + ty + r) * HW_ + j0 + tx];
    __syncthreads();
#pragma unroll
    for (int r = 0; r < 32; r += 8) {
        int j = j0 + ty + r;
        float s = g_scale[z * HW_ + j];
        dst[(size_t)j * D_ + d0 + tx] = __float2bfloat16(tile[tx][ty + r] * s);
    }
}

// ------------------------------ helpers ------------------------------
__device__ __forceinline__ uint32_t smem_u32(const void* p) {
    return (uint32_t)__cvta_generic_to_shared(p);
}

__device__ __forceinline__ void cpasync16(uint32_t dst, const void* src) {
    asm volatile("cp.async.cg.shared.global [%0], [%1], 16;"
                 :: "r"(dst), "l"(src) : "memory");
}

__device__ __forceinline__ void ldsm4(uint32_t& r0, uint32_t& r1,
                                      uint32_t& r2, uint32_t& r3,
                                      uint32_t addr) {
    asm volatile("ldmatrix.sync.aligned.m8n8.x4.shared.b16 {%0,%1,%2,%3}, [%4];"
                 : "=r"(r0), "=r"(r1), "=r"(r2), "=r"(r3) : "r"(addr));
}

__device__ __forceinline__ void mma16816(float* c, const uint32_t* a,
                                         uint32_t b0, uint32_t b1) {
    asm volatile(
        "mma.sync.aligned.m16n8k16.row.col.f32.bf16.bf16.f32 "
        "{%0,%1,%2,%3}, {%4,%5,%6,%7}, {%8,%9}, {%0,%1,%2,%3};"
        : "+f"(c[0]), "+f"(c[1]), "+f"(c[2]), "+f"(c[3])
        : "r"(a[0]), "r"(a[1]), "r"(a[2]), "r"(a[3]), "r"(b0), "r"(b1));
}

#define SWZ(x) ((x) ^ (((x) >> 3) & 0x70))

// SMEM layout: 2 chunk buffers (A 24KB + B 24KB each), then epilogue arrays
#define OFF_BUF    1024
#define CHUNK_BYTES 49152
#define ABUF(b)    (OFF_BUF + (b) * CHUNK_BYTES)
#define OFF_ROWP   (OFF_BUF + 2 * CHUNK_BYTES)        // rowp[2][192] f32
#define OFF_COLP   (OFF_ROWP + 2 * 192 * 4)           // colp[4][192] f32
#define OFF_RED    (OFF_COLP + 4 * 192 * 4)           // red[8]
#define SMEM_BYTES (OFF_RED + 64)

// ------------------------------ Kernel 3: GEMM + fused epilogue ---------------
__global__ void __launch_bounds__(256, 1) qaconv_gemm(
    const float* __restrict__ bnw, const float* __restrict__ bnb,
    const float* __restrict__ bnm, const float* __restrict__ bnv,
    const float* __restrict__ fcw, const float* __restrict__ fcb,
    const float* __restrict__ lbnw, const float* __restrict__ lbnb,
    const float* __restrict__ lbnm, const float* __restrict__ lbnv,
    float* __restrict__ out)
{
    extern __shared__ char smem[];
    const uint32_t sbase = smem_u32(smem);
    const int tid = threadIdx.x;
    const int wid = tid >> 5;
    const int lane = tid & 31;
    const int warp_m = wid & 3;        // 4 strips of 48 rows (probe i)
    const int warp_n = wid >> 2;       // 2 strips of 96 cols (gallery j)
    const int gidx = blockIdx.x >> 6;
    const int pidx = blockIdx.x & 63;

    const __nv_bfloat16* Ag = g_kerA + (size_t)pidx * HW_ * D_;  // [192][512]
    const __nv_bfloat16* Bg = g_galB + (size_t)gidx * HW_ * D_;  // [192][512]

    // accumulators: warp tile 48x96 -> 3 m-tiles(16) x 12 n-tiles(8) x 4 f32
    float acc[3][12][4];
#pragma unroll
    for (int mt = 0; mt < 3; mt++)
#pragma unroll
        for (int nt = 0; nt < 12; nt++)
#pragma unroll
            for (int q = 0; q < 4; q++) acc[mt][nt][q] = 0.f;

    // ------------------ pipelined mainloop: 8 chunks of K=64 ------------------
    // chunk buffer: A rows 0..191 x 128B (swizzled), B likewise at +24576
#define LOAD_CHUNK(c, buf)                                                     \
    {                                                                          \
        const uint32_t ab_ = sbase + ABUF(buf);                                \
        _Pragma("unroll")                                                      \
        for (int i = 0; i < 12; i++) {                                         \
            int gid2 = tid + i * 256;                                          \
            bool isA = gid2 < 1536;                                            \
            int lg = isA ? gid2 : gid2 - 1536;                                 \
            int row = lg >> 3, seg = lg & 7;                                   \
            const __nv_bfloat16* src =                                         \
                (isA ? Ag : Bg) + (size_t)row * D_ + (c) * 64 + seg * 8;       \
            uint32_t dst = ab_ + (isA ? 0 : 24576) + SWZ(row * 128 + seg * 16);\
            cpasync16(dst, src);                                               \
        }                                                                      \
        asm volatile("cp.async.commit_group;" ::: "memory");                   \
    }

    LOAD_CHUNK(0, 0);

#pragma unroll 1
    for (int c = 0; c < 8; c++) {
        const int buf = c & 1;
        if (c < 7) {
            LOAD_CHUNK(c + 1, buf ^ 1);
            asm volatile("cp.async.wait_group 1;" ::: "memory");
        } else {
            asm volatile("cp.async.wait_group 0;" ::: "memory");
        }
        __syncthreads();

        const uint32_t ab = sbase + ABUF(buf);
        const uint32_t bb = ab + 24576;
        const int arowb = (warp_m * 48 + (lane & 15)) * 128;
        const int brow  = warp_n * 96 + (lane & 7) + ((lane >> 4) << 3);
#pragma unroll
        for (int ks = 0; ks < 4; ks++) {
            const int akb = ks * 32 + ((lane >> 4) << 4);
            const int bkb = ks * 32 + (((lane >> 3) & 1) << 4);
            uint32_t a[3][4];
#pragma unroll
            for (int mt = 0; mt < 3; mt++)
                ldsm4(a[mt][0], a[mt][1], a[mt][2], a[mt][3],
                      ab + SWZ(arowb + mt * 2048 + akb));
            uint32_t bf[6][4];
#pragma unroll
            for (int nt2 = 0; nt2 < 6; nt2++)
                ldsm4(bf[nt2][0], bf[nt2][1], bf[nt2][2], bf[nt2][3],
                      bb + SWZ((brow + nt2 * 16) * 128 + bkb));
#pragma unroll
            for (int mt = 0; mt < 3; mt++)
#pragma unroll
                for (int nt2 = 0; nt2 < 6; nt2++) {
                    mma16816(acc[mt][nt2 * 2 + 0], a[mt], bf[nt2][0], bf[nt2][1]);
                    mma16816(acc[mt][nt2 * 2 + 1], a[mt], bf[nt2][2], bf[nt2][3]);
                }
        }
        __syncthreads();
    }

    // ---------------- fused epilogue: dual max + BN/fc/LBN/sigmoid ----------
    // C cell map: acc[mt][nt][q] -> row = warp_m*48 + mt*16 + lane/4 + (q>=2)*8
    //                              col = warp_n*96 + nt*8 + (lane%4)*2 + (q&1)
    float* rowp = (float*)(smem + OFF_ROWP);   // [2][192]  max over j, per i
    float* colp = (float*)(smem + OFF_COLP);   // [4][192]  max over i, per j

    // per-thread row maxes (6 rows), reduce over lane%4 (shared rows)
    float rm[6];
#pragma unroll
    for (int mt = 0; mt < 3; mt++) {
        float r0 = -3.4e38f, r1 = -3.4e38f;
#pragma unroll
        for (int nt = 0; nt < 12; nt++) {
            r0 = fmaxf(r0, fmaxf(acc[mt][nt][0], acc[mt][nt][1]));
            r1 = fmaxf(r1, fmaxf(acc[mt][nt][2], acc[mt][nt][3]));
        }
        rm[2 * mt] = r0; rm[2 * mt + 1] = r1;
    }
#pragma unroll
    for (int i = 0; i < 6; i++) {
        rm[i] = fmaxf(rm[i], __shfl_xor_sync(0xffffffffu, rm[i], 1));
        rm[i] = fmaxf(rm[i], __shfl_xor_sync(0xffffffffu, rm[i], 2));
    }
    if ((lane & 3) == 0) {
        int rbase = warp_m * 48 + (lane >> 2);
#pragma unroll
        for (int mt = 0; mt < 3; mt++) {
            rowp[warp_n * 192 + rbase + mt * 16]     = rm[2 * mt];
            rowp[warp_n * 192 + rbase + mt * 16 + 8] = rm[2 * mt + 1];
        }
    }

    // per-thread col maxes (24 cols), reduce over lane/4 (shared cols)
    float cm[24];
#pragma unroll
    for (int nt = 0; nt < 12; nt++) {
        float c0 = -3.4e38f, c1 = -3.4e38f;
#pragma unroll
        for (int mt = 0; mt < 3; mt++) {
            c0 = fmaxf(c0, fmaxf(acc[mt][nt][0], acc[mt][nt][2]));
            c1 = fmaxf(c1, fmaxf(acc[mt][nt][1], acc[mt][nt][3]));
        }
        cm[2 * nt] = c0; cm[2 * nt + 1] = c1;
    }
#pragma unroll
    for (int i = 0; i < 24; i++) {
        cm[i] = fmaxf(cm[i], __shfl_xor_sync(0xffffffffu, cm[i], 4));
        cm[i] = fmaxf(cm[i], __shfl_xor_sync(0xffffffffu, cm[i], 8));
        cm[i] = fmaxf(cm[i], __shfl_xor_sync(0xffffffffu, cm[i], 16));
    }
    if (lane < 4) {
        int cbase = warp_n * 96 + lane * 2;
#pragma unroll
        for (int nt = 0; nt < 12; nt++) {
            colp[warp_m * 192 + cbase + nt * 8]     = cm[2 * nt];
            colp[warp_m * 192 + cbase + nt * 8 + 1] = cm[2 * nt + 1];
        }
    }
    __syncthreads();

    float a_bn = bnw[0] * rsqrtf(bnv[0] + 1e-5f);
    float b_bn = bnb[0] - bnm[0] * a_bn;

    float part = 0.f;
    if (tid < 192) {
        float cmax = fmaxf(fmaxf(colp[tid], colp[192 + tid]),
                           fmaxf(colp[384 + tid], colp[576 + tid]));  // max over i
        float rmax = fmaxf(rowp[tid], rowp[192 + tid]);               // max over j
        part = fcw[tid]       * (a_bn * cmax + b_bn)     // s.max(axis=2), index j
             + fcw[192 + tid] * (a_bn * rmax + b_bn);    // s.max(axis=3), index i
    }
#pragma unroll
    for (int o = 16; o > 0; o >>= 1)
        part += __shfl_down_sync(0xffffffffu, part, o);
    float* red = (float*)(smem + OFF_RED);
    if (lane == 0) red[wid] = part;
    __syncthreads();
    if (tid == 0) {
        float s = red[0] + red[1] + red[2] + red[3] +
                  red[4] + red[5] + red[6] + red[7];
        s += fcb[0];
        float a2 = lbnw[0] * rsqrtf(lbnv[0] + 1e-5f);
        float y = (s - lbnm[0]) * a2 + lbnb[0];
        out[blockIdx.x] = 1.f / (1.f + expf(-y * 0.1f));
    }
}

// ------------------------------ launch ---------------------------------------
extern "C" void kernel_launch(void* const* d_in, const int* in_sizes, int n_in,
                              void* d_out, int out_size) {
    const float* gal  = (const float*)d_in[0];
    const float* prob = (const float*)d_in[1];
    const float* bnw  = (const float*)d_in[2];
    const float* bnb  = (const float*)d_in[3];
    const float* bnm  = (const float*)d_in[4];
    const float* bnv  = (const float*)d_in[5];
    const float* fcw  = (const float*)d_in[6];
    const float* fcb  = (const float*)d_in[7];
    const float* lbnw = (const float*)d_in[8];
    const float* lbnb = (const float*)d_in[9];
    const float* lbnm = (const float*)d_in[10];
    const float* lbnv = (const float*)d_in[11];
    float* out = (float*)d_out;

    cudaFuncSetAttribute(qaconv_gemm, cudaFuncAttributeMaxDynamicSharedMemorySize,
                         SMEM_BYTES);

    norm_kernel<<<128, 192>>>(gal, prob);
    prep_kernel<<<dim3(16, 6, 128), dim3(32, 8)>>>(gal, prob);
    qaconv_gemm<<<G_ * P_, 256, SMEM_BYTES>>>(bnw, bnb, bnm, bnv, fcw, fcb,
                                              lbnw, lbnb, lbnm, lbnv, out);
}